// round 9
// baseline (speedup 1.0000x reference)
#include <cuda_runtime.h>
#include <cuda_fp16.h>
#include <cstdint>

#define BB 16
#define NN 2048
#define DD 768
#define ROWS (BB*NN)

#define KC 32                  // k elems per chunk
#define NCH (DD/KC)            // 24 chunks per tile item
#define GRID 296               // 148 SMs x 2 CTA/SM, all co-resident
#define NSTAGE 6
#define SUB 8192               // one 128x64B sub-buffer (swizzled)
#define STAGE (2*SUB)
#define SMEM_DYN (NSTAGE*STAGE + 128*8 + 128*4)   // 99840
#define CAP 64
#define MARGIN 4e-4f

#define TPB 304                // tasks per batch block: 32 prep + 256 gemm + 16 rescore(b-1)
#define NTASK (BB*TPB + 16)    // + final 16 rescore tasks for batch 15

// ---- scratch (allocation-free rule: __device__ globals) --------------------
__device__ __align__(16) __half g_Qh[(size_t)ROWS*DD];
__device__ __align__(16) __half g_Ch[(size_t)ROWS*DD];
__device__ float g_invq[ROWS];
__device__ float g_invc[ROWS];
__device__ unsigned long long g_gmax[ROWS];
__device__ int   g_cnt[ROWS];
__device__ int   g_cand[(size_t)ROWS*CAP];
__device__ int   g_prepdone[BB];
__device__ int   g_gemmdone[BB];

// ---------------------------------------------------------------------------
__device__ __forceinline__ uint32_t smem_u32(const void* p) {
    uint32_t a;
    asm("{ .reg .u64 t; cvta.to.shared.u64 t, %1; cvt.u32.u64 %0, t; }" : "=r"(a) : "l"(p));
    return a;
}
__device__ __forceinline__ uint32_t swoff(int row, int piece) {
    return (uint32_t)(((row >> 1) * 128) +
                      ((((((row & 1) << 2) | piece)) ^ ((row >> 1) & 7)) << 4));
}
__device__ __forceinline__ unsigned long long packsc(float v, int col) {
    uint32_t b = __float_as_uint(v);
    uint32_t key = (b & 0x80000000u) ? ~b : (b | 0x80000000u);
    return ((unsigned long long)key << 32) | (uint32_t)(2047 - col);
}
__device__ __forceinline__ float unpack_score(unsigned long long p) {
    uint32_t key = (uint32_t)(p >> 32);
    uint32_t fb = (key & 0x80000000u) ? (key & 0x7FFFFFFFu) : ~key;
    return __uint_as_float(fb);
}

#define LDSM4(r, addr) \
    asm volatile("ldmatrix.sync.aligned.m8n8.x4.shared.b16 {%0,%1,%2,%3}, [%4];" \
        : "=r"((r)[0]), "=r"((r)[1]), "=r"((r)[2]), "=r"((r)[3]) : "r"(addr))

#define MMA16816(d, a, b) \
    asm volatile("mma.sync.aligned.m16n8k16.row.col.f32.f16.f16.f32 " \
        "{%0,%1,%2,%3}, {%4,%5,%6,%7}, {%8,%9}, {%0,%1,%2,%3};" \
        : "+f"((d)[0]), "+f"((d)[1]), "+f"((d)[2]), "+f"((d)[3]) \
        : "r"((a)[0]), "r"((a)[1]), "r"((a)[2]), "r"((a)[3]), "r"((b)[0]), "r"((b)[1]))

#define CP_ASYNC16(dst, src) \
    asm volatile("cp.async.cg.shared.global [%0], [%1], 16;" :: "r"(dst), "l"(src))
#define CP_COMMIT() asm volatile("cp.async.commit_group;" ::: "memory")
#define CP_WAIT4()  asm volatile("cp.async.wait_group 4;" ::: "memory")

// ---------------------------------------------------------------------------
__global__ void init_kernel() {
    if (threadIdx.x < BB) { g_prepdone[threadIdx.x] = 0; g_gemmdone[threadIdx.x] = 0; }
}

// ---------------------------------------------------------------------------
// Fused persistent kernel: prep + gemm + rescore, batch-pipelined.
// ---------------------------------------------------------------------------
__global__ __launch_bounds__(256, 2) void fused_kernel(
    const float* __restrict__ Qi, const float* __restrict__ Qv,
    const float* __restrict__ Ci, const float* __restrict__ Cv,
    const float* __restrict__ thr_raw, float* __restrict__ out) {
    extern __shared__ __align__(1024) unsigned char smem[];
    const uint32_t sb = smem_u32(smem);
    unsigned long long* table = (unsigned long long*)(smem + NSTAGE * STAGE);
    float* tableF = (float*)(smem + NSTAGE * STAGE + 128 * 8);

    const int tid = threadIdx.x, wid = tid >> 5, lane = tid & 31;

    for (int t = blockIdx.x; t < NTASK; t += GRID) {
        int b, u;
        if (t >= BB * TPB) { b = 16; u = 288 + (t - BB * TPB); }  // final rescore(15)
        else { b = t / TPB; u = t - b * TPB; }

        if (u < 32) {
            // ================= PREP task: 128 rows of one side =================
            const bool isC = (u >= 16);
            const int r0 = b * NN + (u & 15) * 128;
            const float* srcb = isC ? Ci : Qi;
            __half* dstb = isC ? g_Ch : g_Qh;
            for (int i = 0; i < 16; i++) {
                const int r = r0 + wid * 16 + i;
                const float4* src = (const float4*)(srcb + (size_t)r * DD);
                float4 v[6]; float ss = 0.f;
#pragma unroll
                for (int q = 0; q < 6; q++) {
                    v[q] = src[lane + 32 * q];
                    ss += v[q].x * v[q].x + v[q].y * v[q].y + v[q].z * v[q].z + v[q].w * v[q].w;
                }
#pragma unroll
                for (int o = 16; o > 0; o >>= 1) ss += __shfl_xor_sync(~0u, ss, o);
                float inv = rsqrtf(ss);
                inv = inv * (1.5f - 0.5f * ss * inv * inv);   // Newton -> ~fp32 exact
                __half* dst = dstb + (size_t)r * DD;
#pragma unroll
                for (int q = 0; q < 6; q++) {
                    __half2 h0 = __floats2half2_rn(v[q].x * inv, v[q].y * inv);
                    __half2 h1 = __floats2half2_rn(v[q].z * inv, v[q].w * inv);
                    uint2 o2;
                    o2.x = *(uint32_t*)&h0; o2.y = *(uint32_t*)&h1;
                    ((uint2*)dst)[lane + 32 * q] = o2;
                }
                if (lane == 0) {
                    if (isC) g_invc[r] = inv;
                    else { g_invq[r] = inv; g_cnt[r] = 0; g_gmax[r] = 0ull; }
                }
            }
            __syncthreads();
            if (tid == 0) { __threadfence(); atomicAdd(&g_prepdone[b], 1); }
        } else if (u < 288) {
            // ================= GEMM task: one 128x128 tile =================
            const int idx = u - 32;
            const int mt = idx >> 4, nt = idx & 15;
            const int wm = wid & 1, wn = wid >> 1;
            const int qrow0 = b * NN + mt * 128;

            if (tid < 128) table[tid] = 0ull;
            if (tid == 0) {
                while (atomicAdd(&g_prepdone[b], 0) < 32) __nanosleep(64);
                __threadfence();
            }
            __syncthreads();

            float acc[4][4][4];
#pragma unroll
            for (int i = 0; i < 4; i++)
#pragma unroll
                for (int j = 0; j < 4; j++)
#pragma unroll
                    for (int c = 0; c < 4; c++) acc[i][j][c] = 0.f;

            const __half* abase0 = g_Qh + (size_t)(b * NN + mt * 128) * DD;
            const __half* bbase0 = g_Ch + (size_t)(b * NN + nt * 128) * DD;
            const int row_l = (tid * 2) >> 2;       // rows loaded by this thread
            const int q0 = (tid * 2) & 3;
            const uint32_t so0 = swoff(row_l, q0);
            const uint32_t so1 = swoff(row_l, q0 + 1);

            // prologue: stages 0..4 = chunks 0..4
#pragma unroll
            for (int j = 0; j < 5; j++) {
                const uint32_t stage = sb + (uint32_t)j * STAGE;
                const __half* ab = abase0 + j * KC;
                const __half* bbs = bbase0 + j * KC;
                CP_ASYNC16(stage + so0,       ab + (size_t)row_l * DD + q0 * 8);
                CP_ASYNC16(stage + so1,       ab + (size_t)row_l * DD + (q0 + 1) * 8);
                CP_ASYNC16(stage + SUB + so0, bbs + (size_t)row_l * DD + q0 * 8);
                CP_ASYNC16(stage + SUB + so1, bbs + (size_t)row_l * DD + (q0 + 1) * 8);
                CP_COMMIT();
            }

            int cs = 0, is = 5;
            for (int f = 0; f < NCH; f++) {
                CP_WAIT4();
                __syncthreads();
                const uint32_t abase = sb + (uint32_t)cs * STAGE;
#pragma unroll
                for (int kk = 0; kk < 2; kk++) {
                    uint32_t ah[4][4], bh[4][2];
                    const int lr = lane & 15, lp = lane >> 4;
#pragma unroll
                    for (int i = 0; i < 4; i++)
                        LDSM4(ah[i], abase + swoff(wm * 64 + i * 16 + lr, kk * 2 + lp));
#pragma unroll
                    for (int jp = 0; jp < 2; jp++) {
                        const int nrow = wn * 32 + (jp * 2 + (lane >> 4)) * 8 + (lane & 7);
                        const int piece = kk * 2 + ((lane >> 3) & 1);
                        uint32_t r4[4];
                        LDSM4(r4, abase + SUB + swoff(nrow, piece));
                        bh[jp*2][0]=r4[0]; bh[jp*2][1]=r4[1];
                        bh[jp*2+1][0]=r4[2]; bh[jp*2+1][1]=r4[3];
                    }
#pragma unroll
                    for (int i = 0; i < 4; i++)
#pragma unroll
                        for (int j = 0; j < 4; j++)
                            MMA16816(acc[i][j], ah[i], bh[j]);
                }
                if (f + 5 < NCH) {
                    const uint32_t stage = sb + (uint32_t)is * STAGE;
                    const __half* ab = abase0 + (f + 5) * KC;
                    const __half* bbs = bbase0 + (f + 5) * KC;
                    CP_ASYNC16(stage + so0,       ab + (size_t)row_l * DD + q0 * 8);
                    CP_ASYNC16(stage + so1,       ab + (size_t)row_l * DD + (q0 + 1) * 8);
                    CP_ASYNC16(stage + SUB + so0, bbs + (size_t)row_l * DD + q0 * 8);
                    CP_ASYNC16(stage + SUB + so1, bbs + (size_t)row_l * DD + (q0 + 1) * 8);
                    CP_COMMIT();
                    is = (is == 5) ? 0 : is + 1;
                }
                cs = (cs == 5) ? 0 : cs + 1;
            }

            // ---- epilogue ----
            const int colbase = nt * 128 + wn * 32 + (lane & 3) * 2;
#pragma unroll
            for (int i = 0; i < 4; i++)
#pragma unroll
                for (int half = 0; half < 2; half++) {
                    float bv = -3.0e38f; int bc = 0;
#pragma unroll
                    for (int j = 0; j < 4; j++) {
                        const int c0 = colbase + j * 8;
                        float v0 = acc[i][j][half * 2 + 0];
                        if (v0 > bv) { bv = v0; bc = c0; }
                        float v1 = acc[i][j][half * 2 + 1];
                        if (v1 > bv) { bv = v1; bc = c0 + 1; }
                    }
#pragma unroll
                    for (int off = 1; off < 4; off <<= 1) {
                        float ov = __shfl_xor_sync(~0u, bv, off);
                        int   oc = __shfl_xor_sync(~0u, bc, off);
                        if (ov > bv || (ov == bv && oc < bc)) { bv = ov; bc = oc; }
                    }
                    if ((lane & 3) == 0) {
                        const int rloc = wm * 64 + i * 16 + half * 8 + (lane >> 2);
                        atomicMax(&table[rloc], packsc(bv, bc));
                    }
                }
            __syncthreads();
            if (tid < 128) {
                unsigned long long loc = table[tid];
                unsigned long long old = atomicMax(&g_gmax[qrow0 + tid], loc);
                if (old > loc) loc = old;
                tableF[tid] = unpack_score(loc) - MARGIN;
            }
            __syncthreads();
#pragma unroll
            for (int i = 0; i < 4; i++)
#pragma unroll
                for (int half = 0; half < 2; half++) {
                    const int rloc = wm * 64 + i * 16 + half * 8 + (lane >> 2);
                    const float cut = tableF[rloc];
                    const int rg = qrow0 + rloc;
#pragma unroll
                    for (int j = 0; j < 4; j++)
#pragma unroll
                        for (int c = 0; c < 2; c++) {
                            float v = acc[i][j][half * 2 + c];
                            if (v >= cut) {
                                int slot = atomicAdd(&g_cnt[rg], 1);
                                if (slot < CAP)
                                    g_cand[(size_t)rg * CAP + slot] = colbase + j * 8 + c;
                            }
                        }
                }
            __syncthreads();
            if (tid == 0) { __threadfence(); atomicAdd(&g_gemmdone[b], 1); }
        } else {
            // ================= RESCORE task: 128 rows of batch (b-1) =================
            const int rb = b - 1;          // b==16 -> rb==15 (final block)
            if (rb < 0) { __syncthreads(); continue; }
            const int r0 = rb * NN + (u - 288) * 128;
            if (tid == 0) {
                while (atomicAdd(&g_gemmdone[rb], 0) < 256) __nanosleep(128);
                __threadfence();
            }
            __syncthreads();
            for (int i = 0; i < 16; i++) {
                const int r = r0 + wid * 16 + i;
                const int n = r & (NN - 1);
                int cnt = g_cnt[r]; if (cnt > CAP) cnt = CAP;
                const float invq = g_invq[r];
                const float4* q4p = (const float4*)(Qi + (size_t)r * DD);
                float4 q4[6];
#pragma unroll
                for (int q = 0; q < 6; q++) q4[q] = q4p[lane + 32 * q];
                unsigned long long best = 0ull;
                for (int ci = 0; ci < cnt; ci++) {
                    const int idx = g_cand[(size_t)r * CAP + ci];
                    const float4* crow = (const float4*)(Ci + ((size_t)(rb * NN + idx)) * DD);
                    float s = 0.f;
#pragma unroll
                    for (int q = 0; q < 6; q++) {
                        float4 cv = crow[lane + 32 * q];
                        s += cv.x * q4[q].x + cv.y * q4[q].y + cv.z * q4[q].z + cv.w * q4[q].w;
                    }
#pragma unroll
                    for (int o = 16; o > 0; o >>= 1) s += __shfl_xor_sync(~0u, s, o);
                    unsigned long long p = packsc(s * invq * g_invc[rb * NN + idx], idx);
                    if (p > best) best = p;
                }
                const float score = unpack_score(best);
                const int bidx = 2047 - (int)(uint32_t)(best & 0xFFFFFFFFull);
                const float thr = 1.f / (1.f + expf(-thr_raw[n]));
                const float rm  = 1.f / (1.f + expf(-40.f * (score - thr)));
                const float om  = 1.f - rm;
                const float4* qv = (const float4*)(Qv + (size_t)r * DD);
                const float4* cb = (const float4*)(Ci + ((size_t)rb * NN + bidx) * DD);
                const float4* cv = (const float4*)(Cv + ((size_t)rb * NN + bidx) * DD);
                float4* oi = (float4*)(out + ROWS + (size_t)r * DD);
                float4* ov = (float4*)(out + ROWS + (size_t)ROWS * DD + (size_t)r * DD);
#pragma unroll
                for (int q = 0; q < 6; q++) {
                    const int e = lane + 32 * q;
                    float4 a = q4[q], c = cb[e];
                    oi[e] = make_float4(om * a.x + rm * c.x, om * a.y + rm * c.y,
                                        om * a.z + rm * c.z, om * a.w + rm * c.w);
                    float4 av = qv[e], cc = cv[e];
                    ov[e] = make_float4(om * av.x + rm * cc.x, om * av.y + rm * cc.y,
                                        om * av.z + rm * cc.z, om * av.w + rm * cc.w);
                }
                if (lane == 0) out[r] = rm;
            }
        }
        __syncthreads();   // task boundary
    }
}

// ---------------------------------------------------------------------------
extern "C" void kernel_launch(void* const* d_in, const int* in_sizes, int n_in,
                              void* d_out, int out_size) {
    const float* Qi = (const float*)d_in[0];
    const float* Qv = (const float*)d_in[1];
    const float* Ci = (const float*)d_in[2];
    const float* Cv = (const float*)d_in[3];
    const float* Th = (const float*)d_in[4];
    float* out = (float*)d_out;

    cudaFuncSetAttribute(fused_kernel,
                         cudaFuncAttributeMaxDynamicSharedMemorySize, SMEM_DYN);

    init_kernel<<<1, 32>>>();
    fused_kernel<<<GRID, 256, SMEM_DYN>>>(Qi, Qv, Ci, Cv, Th, out);
}

// round 10
// speedup vs baseline: 2.2842x; 2.2842x over previous
#include <cuda_runtime.h>
#include <cuda_fp16.h>
#include <cstdint>

#define BB 16
#define NN 2048
#define DD 768
#define ROWS (BB*NN)

#define KC 32                  // k elems per chunk
#define NCH (DD/KC)            // 24 chunks per tile item
#define NITEMS (BB*16*16)      // 4096 (b, mt, nt) 128x128 tiles
#define GRID 296               // 148 SMs x 2 CTA/SM (persistent)
#define NSTAGE 6
#define SUB 8192               // one 128x32 fp16 sub-buffer (swizzled)
#define STAGE (2*SUB)          // A, B
#define SMEM_DYN (NSTAGE*STAGE + 128*8 + 128*4)   // 99840
#define CAP 64
#define MARGIN 4e-4f

// ---- scratch (allocation-free rule: __device__ globals) --------------------
__device__ __align__(16) __half g_Qh[(size_t)ROWS*DD];  // fp16(q/||q||)
__device__ __align__(16) __half g_Ch[(size_t)ROWS*DD];  // fp16(c/||c||)
__device__ float g_invq[ROWS];
__device__ float g_invc[ROWS];
__device__ unsigned long long g_gmax[ROWS];
__device__ int   g_cnt[ROWS];
__device__ int   g_cand[(size_t)ROWS*CAP];

// ---------------------------------------------------------------------------
__device__ __forceinline__ uint32_t smem_u32(const void* p) {
    uint32_t a;
    asm("{ .reg .u64 t; cvta.to.shared.u64 t, %1; cvt.u32.u64 %0, t; }" : "=r"(a) : "l"(p));
    return a;
}
// swizzled offset inside one 128-row x 64B sub-buffer (conflict-free LDSM+STS)
__device__ __forceinline__ uint32_t swoff(int row, int piece) {
    return (uint32_t)(((row >> 1) * 128) +
                      ((((((row & 1) << 2) | piece)) ^ ((row >> 1) & 7)) << 4));
}
__device__ __forceinline__ unsigned long long packsc(float v, int col) {
    uint32_t b = __float_as_uint(v);
    uint32_t key = (b & 0x80000000u) ? ~b : (b | 0x80000000u);
    return ((unsigned long long)key << 32) | (uint32_t)(2047 - col);
}
__device__ __forceinline__ float unpack_score(unsigned long long p) {
    uint32_t key = (uint32_t)(p >> 32);
    uint32_t fb = (key & 0x80000000u) ? (key & 0x7FFFFFFFu) : ~key;
    return __uint_as_float(fb);
}

#define LDSM4(r, addr) \
    asm volatile("ldmatrix.sync.aligned.m8n8.x4.shared.b16 {%0,%1,%2,%3}, [%4];" \
        : "=r"((r)[0]), "=r"((r)[1]), "=r"((r)[2]), "=r"((r)[3]) : "r"(addr))

#define MMA16816(d, a, b) \
    asm volatile("mma.sync.aligned.m16n8k16.row.col.f32.f16.f16.f32 " \
        "{%0,%1,%2,%3}, {%4,%5,%6,%7}, {%8,%9}, {%0,%1,%2,%3};" \
        : "+f"((d)[0]), "+f"((d)[1]), "+f"((d)[2]), "+f"((d)[3]) \
        : "r"((a)[0]), "r"((a)[1]), "r"((a)[2]), "r"((a)[3]), "r"((b)[0]), "r"((b)[1]))

#define CP_ASYNC16(dst, src) \
    asm volatile("cp.async.cg.shared.global [%0], [%1], 16;" :: "r"(dst), "l"(src))
#define CP_COMMIT() asm volatile("cp.async.commit_group;" ::: "memory")
#define CP_WAIT4()  asm volatile("cp.async.wait_group 4;" ::: "memory")

// ---------------------------------------------------------------------------
// Prepass: warp per row. Row in registers, shfl reduction, no smem/barriers.
// grid: 2*ROWS/8 blocks of 256 (8 warps). gwarp < ROWS -> Q, else C.
// ---------------------------------------------------------------------------
__global__ __launch_bounds__(256) void prep_kernel(const float* __restrict__ Qi,
                                                   const float* __restrict__ Ci) {
    const int gwarp = blockIdx.x * 8 + (threadIdx.x >> 5);
    const int lane = threadIdx.x & 31;
    const bool isC = gwarp >= ROWS;
    const int r = isC ? (gwarp - ROWS) : gwarp;
    const float4* src = (const float4*)((isC ? Ci : Qi) + (size_t)r * DD);
    float4 v[6]; float ss = 0.f;
#pragma unroll
    for (int q = 0; q < 6; q++) {
        v[q] = src[lane + 32 * q];
        ss += v[q].x * v[q].x + v[q].y * v[q].y + v[q].z * v[q].z + v[q].w * v[q].w;
    }
#pragma unroll
    for (int o = 16; o > 0; o >>= 1) ss += __shfl_xor_sync(~0u, ss, o);
    float inv = rsqrtf(ss);
    inv = inv * (1.5f - 0.5f * ss * inv * inv);   // Newton -> ~fp32 exact
    __half* dst = (isC ? g_Ch : g_Qh) + (size_t)r * DD;
#pragma unroll
    for (int q = 0; q < 6; q++) {
        __half2 h0 = __floats2half2_rn(v[q].x * inv, v[q].y * inv);
        __half2 h1 = __floats2half2_rn(v[q].z * inv, v[q].w * inv);
        uint2 u; u.x = *(uint32_t*)&h0; u.y = *(uint32_t*)&h1;
        ((uint2*)dst)[lane + 32 * q] = u;
    }
    if (lane == 0) {
        if (isC) g_invc[r] = inv;
        else { g_invq[r] = inv; g_cnt[r] = 0; g_gmax[r] = 0ull; }
    }
}

// ---------------------------------------------------------------------------
// Persistent fp16 approx GEMM + margin candidate collection (R6, unchanged).
// 296 CTAs, 256 thr, 2 CTA/SM. Items = 4096 (b, mt, nt) 128x128 tiles,
// strided: item = cta + k*GRID. 6-stage cp.async pipeline, K in 24 chunks.
// ---------------------------------------------------------------------------
__global__ __launch_bounds__(256, 2) void gemm_kernel() {
    extern __shared__ __align__(1024) unsigned char smem[];
    const uint32_t sb = smem_u32(smem);
    unsigned long long* table = (unsigned long long*)(smem + NSTAGE * STAGE);
    float* tableF = (float*)(smem + NSTAGE * STAGE + 128 * 8);

    const int cta = blockIdx.x;
    const int tid = threadIdx.x, wid = tid >> 5, lane = tid & 31;
    const int wm = wid & 1, wn = wid >> 1;

    const int nit = (NITEMS - cta + GRID - 1) / GRID;
    const int nch_tot = nit * NCH;

    if (tid < 128) table[tid] = 0ull;
    __syncthreads();

    float acc[4][4][4];
#pragma unroll
    for (int i = 0; i < 4; i++)
#pragma unroll
        for (int j = 0; j < 4; j++)
#pragma unroll
            for (int c = 0; c < 4; c++) acc[i][j][c] = 0.f;

    auto issue_chunk = [&](int f, int stage_idx) {
        const int il = f / NCH, kc = f - il * NCH;
        const int item = cta + il * GRID;
        const int b = item >> 8, mt = (item >> 4) & 15, nt = item & 15;
        const uint32_t stage = sb + (uint32_t)stage_idx * STAGE;
        const __half* abase = g_Qh + (size_t)(b * NN + mt * 128) * DD + kc * KC;
        const __half* bbase = g_Ch + (size_t)(b * NN + nt * 128) * DD + kc * KC;
#pragma unroll
        for (int pp = 0; pp < 2; pp++) {
            const int p = tid * 2 + pp;
            const int row = p >> 2, q = p & 3;
            const uint32_t so = swoff(row, q);
            CP_ASYNC16(stage + so,       abase + (size_t)row * DD + q * 8);
            CP_ASYNC16(stage + SUB + so, bbase + (size_t)row * DD + q * 8);
        }
        CP_COMMIT();
    };

    // prologue: 5 chunks into stages 0..4
#pragma unroll
    for (int j = 0; j < 5; j++) issue_chunk(j, j);

    int cs = 0, is = 5;   // consume / issue stage (mod 6, rolling)
    for (int f = 0; f < nch_tot; f++) {
        CP_WAIT4();
        __syncthreads();
        const uint32_t abase = sb + (uint32_t)cs * STAGE;
#pragma unroll
        for (int kk = 0; kk < 2; kk++) {
            uint32_t ah[4][4], bh[4][2];
            const int lr = lane & 15, lp = lane >> 4;
#pragma unroll
            for (int i = 0; i < 4; i++)
                LDSM4(ah[i], abase + swoff(wm * 64 + i * 16 + lr, kk * 2 + lp));
#pragma unroll
            for (int jp = 0; jp < 2; jp++) {
                const int nrow = wn * 32 + (jp * 2 + (lane >> 4)) * 8 + (lane & 7);
                const int piece = kk * 2 + ((lane >> 3) & 1);
                uint32_t r4[4];
                LDSM4(r4, abase + SUB + swoff(nrow, piece));
                bh[jp*2][0]=r4[0]; bh[jp*2][1]=r4[1]; bh[jp*2+1][0]=r4[2]; bh[jp*2+1][1]=r4[3];
            }
#pragma unroll
            for (int i = 0; i < 4; i++)
#pragma unroll
                for (int j = 0; j < 4; j++)
                    MMA16816(acc[i][j], ah[i], bh[j]);
        }
        if (f + 5 < nch_tot) { issue_chunk(f + 5, is); is = (is == 5) ? 0 : is + 1; }
        cs = (cs == 5) ? 0 : cs + 1;

        const int il = f / NCH;
        if (f - il * NCH == NCH - 1) {
            const int item = cta + il * GRID;
            const int b = item >> 8, mt = (item >> 4) & 15, nt = item & 15;
            const int qrow0 = b * NN + mt * 128;
            const int colbase = nt * 128 + wn * 32 + (lane & 3) * 2;
            // phase 1: per-row tile max into smem table
#pragma unroll
            for (int i = 0; i < 4; i++)
#pragma unroll
                for (int half = 0; half < 2; half++) {
                    float bv = -3.0e38f; int bc = 0;
#pragma unroll
                    for (int j = 0; j < 4; j++) {
                        const int c0 = colbase + j * 8;
                        float v0 = acc[i][j][half * 2 + 0];
                        if (v0 > bv) { bv = v0; bc = c0; }
                        float v1 = acc[i][j][half * 2 + 1];
                        if (v1 > bv) { bv = v1; bc = c0 + 1; }
                    }
#pragma unroll
                    for (int off = 1; off < 4; off <<= 1) {
                        float ov = __shfl_xor_sync(~0u, bv, off);
                        int   oc = __shfl_xor_sync(~0u, bc, off);
                        if (ov > bv || (ov == bv && oc < bc)) { bv = ov; bc = oc; }
                    }
                    if ((lane & 3) == 0) {
                        const int rloc = wm * 64 + i * 16 + half * 8 + (lane >> 2);
                        atomicMax(&table[rloc], packsc(bv, bc));
                    }
                }
            __syncthreads();
            // merge with global running row max -> cut
            if (tid < 128) {
                unsigned long long loc = table[tid];
                unsigned long long old = atomicMax(&g_gmax[qrow0 + tid], loc);
                if (old > loc) loc = old;
                tableF[tid] = unpack_score(loc) - MARGIN;
            }
            __syncthreads();
            // phase 2: append candidates >= cut
#pragma unroll
            for (int i = 0; i < 4; i++)
#pragma unroll
                for (int half = 0; half < 2; half++) {
                    const int rloc = wm * 64 + i * 16 + half * 8 + (lane >> 2);
                    const float cut = tableF[rloc];
                    const int rg = qrow0 + rloc;
#pragma unroll
                    for (int j = 0; j < 4; j++)
#pragma unroll
                        for (int c = 0; c < 2; c++) {
                            float v = acc[i][j][half * 2 + c];
                            if (v >= cut) {
                                int slot = atomicAdd(&g_cnt[rg], 1);
                                if (slot < CAP)
                                    g_cand[(size_t)rg * CAP + slot] = colbase + j * 8 + c;
                            }
                        }
                }
            __syncthreads();
            if (tid < 128) table[tid] = 0ull;
            // next table use is >= 24 chunks away, separated by syncs.
#pragma unroll
            for (int i = 0; i < 4; i++)
#pragma unroll
                for (int j = 0; j < 4; j++)
#pragma unroll
                    for (int c = 0; c < 4; c++) acc[i][j][c] = 0.f;
        }
    }
}

// ---------------------------------------------------------------------------
// Fused exact rescore + blend: warp per row, no block barriers.
// grid ROWS/8 blocks of 256 (8 warps). q row cached in registers.
// out layout: [reuse_map (B*N)] [reuse_input (B*N*D)] [reuse_value (B*N*D)]
// ---------------------------------------------------------------------------
__global__ __launch_bounds__(256) void rescore_blend_kernel(
    const float* __restrict__ Qi, const float* __restrict__ Qv,
    const float* __restrict__ Ci, const float* __restrict__ Cv,
    const float* __restrict__ thr_raw, float* __restrict__ out) {
    const int r = blockIdx.x * 8 + (threadIdx.x >> 5);
    const int lane = threadIdx.x & 31;
    const int b = r >> 11;
    const int n = r & (NN - 1);

    const float4* q4p = (const float4*)(Qi + (size_t)r * DD);
    float4 q4[6];
#pragma unroll
    for (int q = 0; q < 6; q++) q4[q] = q4p[lane + 32 * q];

    int cnt = g_cnt[r]; if (cnt > CAP) cnt = CAP;
    const float invq = g_invq[r];
    unsigned long long best = 0ull;
    for (int ci = 0; ci < cnt; ci++) {
        const int idx = g_cand[(size_t)r * CAP + ci];
        const float4* crow = (const float4*)(Ci + ((size_t)(b * NN + idx)) * DD);
        float s = 0.f;
#pragma unroll
        for (int q = 0; q < 6; q++) {
            float4 cv = crow[lane + 32 * q];
            s += cv.x * q4[q].x + cv.y * q4[q].y + cv.z * q4[q].z + cv.w * q4[q].w;
        }
#pragma unroll
        for (int o = 16; o > 0; o >>= 1) s += __shfl_xor_sync(~0u, s, o);
        unsigned long long p = packsc(s * invq * g_invc[b * NN + idx], idx);
        if (p > best) best = p;       // identical on all lanes
    }
    const float score = unpack_score(best);
    const int idx = 2047 - (int)(uint32_t)(best & 0xFFFFFFFFull);
    const float thr = 1.f / (1.f + expf(-thr_raw[n]));
    const float rm  = 1.f / (1.f + expf(-40.f * (score - thr)));
    const float om  = 1.f - rm;

    const float4* qv = (const float4*)(Qv + (size_t)r * DD);
    const float4* cb = (const float4*)(Ci + ((size_t)b * NN + idx) * DD);
    const float4* cv = (const float4*)(Cv + ((size_t)b * NN + idx) * DD);
    float4* oi = (float4*)(out + ROWS + (size_t)r * DD);
    float4* ov = (float4*)(out + ROWS + (size_t)ROWS * DD + (size_t)r * DD);
#pragma unroll
    for (int q = 0; q < 6; q++) {
        const int e = lane + 32 * q;
        float4 a = q4[q], c = cb[e];
        oi[e] = make_float4(om * a.x + rm * c.x, om * a.y + rm * c.y,
                            om * a.z + rm * c.z, om * a.w + rm * c.w);
        float4 av = qv[e], cc = cv[e];
        ov[e] = make_float4(om * av.x + rm * cc.x, om * av.y + rm * cc.y,
                            om * av.z + rm * cc.z, om * av.w + rm * cc.w);
    }
    if (lane == 0) out[r] = rm;
}

// ---------------------------------------------------------------------------
extern "C" void kernel_launch(void* const* d_in, const int* in_sizes, int n_in,
                              void* d_out, int out_size) {
    const float* Qi = (const float*)d_in[0];
    const float* Qv = (const float*)d_in[1];
    const float* Ci = (const float*)d_in[2];
    const float* Cv = (const float*)d_in[3];
    const float* Th = (const float*)d_in[4];
    float* out = (float*)d_out;

    cudaFuncSetAttribute(gemm_kernel,
                         cudaFuncAttributeMaxDynamicSharedMemorySize, SMEM_DYN);

    prep_kernel<<<(2 * ROWS) / 8, 256>>>(Qi, Ci);
    gemm_kernel<<<GRID, 256, SMEM_DYN>>>();
    rescore_blend_kernel<<<ROWS / 8, 256>>>(Qi, Qv, Ci, Cv, Th, out);
}